// round 9
// baseline (speedup 1.0000x reference)
#include <cuda_runtime.h>
#include <cuda_bf16.h>
#include <math.h>

#define NN 4096
#define EE 16384
#define PHID 64
#define EPSF 1e-8f
#define CAP 32

// Q = round(B/scale_r) int8 (16MB, L2-resident); per-row c = scale_r/d_r.
__device__ char g_Q[(size_t)NN * NN];
__device__ float g_c[NN];
// per-(layer,node) edge lists via atomic append; all bookkeeping state below
// starts zero (BSS) and is restored to zero every call -> replay-invariant.
__device__ int g_cnt[2 * NN];
__device__ int g_list[2 * NN * CAP];
__device__ int g_start2[2 * NN + 1];
__device__ int g_nodeof[2 * EE];
__device__ int g_done;

// ---------------------------------------------------------------------------
// k_prep: 2 rows per CTA in registers; f_mean in registers; fused reductions;
// free list append; LAST-DONE CTA runs the 8192-bin scan + slot->node emit.
// ---------------------------------------------------------------------------
__global__ __launch_bounds__(256) void k_prep(const float* __restrict__ A,
                                              const float* __restrict__ f0,
                                              const float* __restrict__ f1,
                                              const int* __restrict__ src0,
                                              const int* __restrict__ src1) {
    __shared__ float rsum[2][8];
    __shared__ float rmax[2][8];
    __shared__ float s_cinv[2];
    __shared__ int s_last;
    __shared__ int s_wscan[8];
    int tid = threadIdx.x;
    int wid = tid >> 5, lane = tid & 31;

    // edge-list append: 2048 CTAs x 16 edges = 32768 = 2*EE
    if (tid < 16) {
        int idx = blockIdx.x * 16 + tid;
        int layer = idx >> 14;
        int e = idx & (EE - 1);
        int s = layer ? __ldg(src1 + e) : __ldg(src0 + e);
        int slot = layer * NN + s;
        int pos = atomicAdd(&g_cnt[slot], 1);
        if (pos < CAP) g_list[slot * CAP + pos] = e;
    }

    float4 f[4];
#pragma unroll
    for (int it = 0; it < 4; ++it) {
        int q = tid + it * 256;
        float4 a = ((const float4*)f0)[q];
        float4 b = ((const float4*)f1)[q];
        f[it].x = 0.5f * (a.x + b.x);
        f[it].y = 0.5f * (a.y + b.y);
        f[it].z = 0.5f * (a.z + b.z);
        f[it].w = 0.5f * (a.w + b.w);
    }

    float4 m[2][4];
    float acc[2], vmax[2];
#pragma unroll
    for (int r = 0; r < 2; ++r) {
        int row = blockIdx.x * 2 + r;
        const float4* a4 = (const float4*)(A + (size_t)row * NN);
        acc[r] = 0.f;
        vmax[r] = 0.f;
#pragma unroll
        for (int it = 0; it < 4; ++it) {
            float4 v = a4[tid + it * 256];
            m[r][it].x = v.x * f[it].x;
            m[r][it].y = v.y * f[it].y;
            m[r][it].z = v.z * f[it].z;
            m[r][it].w = v.w * f[it].w;
            float e0 = m[r][it].x + EPSF, e1 = m[r][it].y + EPSF;
            float e2 = m[r][it].z + EPSF, e3 = m[r][it].w + EPSF;
            acc[r] += e0 * e0 + e1 * e1 + e2 * e2 + e3 * e3;
            vmax[r] = fmaxf(vmax[r],
                            fmaxf(fmaxf(fabsf(m[r][it].x), fabsf(m[r][it].y)),
                                  fmaxf(fabsf(m[r][it].z), fabsf(m[r][it].w))));
        }
    }
#pragma unroll
    for (int off = 16; off; off >>= 1) {
#pragma unroll
        for (int r = 0; r < 2; ++r) {
            acc[r] += __shfl_xor_sync(0xffffffffu, acc[r], off);
            vmax[r] = fmaxf(vmax[r], __shfl_xor_sync(0xffffffffu, vmax[r], off));
        }
    }
    if (lane == 0) {
#pragma unroll
        for (int r = 0; r < 2; ++r) {
            rsum[r][wid] = acc[r];
            rmax[r][wid] = vmax[r];
        }
    }
    __syncthreads();
    if (tid < 2) {
        float t = 0.f, mx = 0.f;
#pragma unroll
        for (int w = 0; w < 8; w++) {
            t += rsum[tid][w];
            mx = fmaxf(mx, rmax[tid][w]);
        }
        float scale = fmaxf(mx, 1e-20f) * (1.0f / 127.0f);
        g_c[blockIdx.x * 2 + tid] = scale / sqrtf(t);
        s_cinv[tid] = 1.0f / scale;
    }
    __syncthreads();

#pragma unroll
    for (int r = 0; r < 2; ++r) {
        float inv_scale = s_cinv[r];
        uchar4 pk[4];
#pragma unroll
        for (int it = 0; it < 4; ++it) {
            int q0 = __float2int_rn(m[r][it].x * inv_scale);
            int q1 = __float2int_rn(m[r][it].y * inv_scale);
            int q2 = __float2int_rn(m[r][it].z * inv_scale);
            int q3 = __float2int_rn(m[r][it].w * inv_scale);
            pk[it].x = (unsigned char)(char)max(-127, min(127, q0));
            pk[it].y = (unsigned char)(char)max(-127, min(127, q1));
            pk[it].z = (unsigned char)(char)max(-127, min(127, q2));
            pk[it].w = (unsigned char)(char)max(-127, min(127, q3));
        }
        uint4 o;
        o.x = *(unsigned*)&pk[0];
        o.y = *(unsigned*)&pk[1];
        o.z = *(unsigned*)&pk[2];
        o.w = *(unsigned*)&pk[3];
        // fixed column permutation: dot/norm-invariant (both rows of an edge
        // share the same packing)
        ((uint4*)(g_Q + (size_t)(blockIdx.x * 2 + r) * NN))[tid] = o;
    }

    // ---- last-done-CTA tail: scan 8192 degs, emit slot->node map ----
    __threadfence();
    __syncthreads();
    if (tid == 0) s_last = (atomicAdd(&g_done, 1) == 2047);
    __syncthreads();
    if (!s_last) return;
    __threadfence();  // acquire side

    // each thread owns 32 bins [tid*32, tid*32+32)
    int base = tid * 32;
    int sum = 0;
#pragma unroll 4
    for (int k = 0; k < 32; ++k) sum += min(g_cnt[base + k], CAP);
    // block exclusive scan of per-thread sums
    int x = sum;
#pragma unroll
    for (int o = 1; o < 32; o <<= 1) {
        int y = __shfl_up_sync(0xffffffffu, x, o);
        if (lane >= o) x += y;
    }
    if (lane == 31) s_wscan[wid] = x;
    __syncthreads();
    if (wid == 0 && lane < 8) {
        int w = s_wscan[lane];
#pragma unroll
        for (int o = 1; o < 8; o <<= 1) {
            int y = __shfl_up_sync(0xffu, w, o);
            if (lane >= o) w += y;
        }
        s_wscan[lane] = w;
    }
    __syncthreads();
    int run = x - sum + (wid ? s_wscan[wid - 1] : 0);
    for (int k = 0; k < 32; ++k) {
        int bin = base + k;
        int d = min(g_cnt[bin], CAP);
        g_cnt[bin] = 0;                 // restore zero invariant
        g_start2[bin] = run;
        for (int i = 0; i < d; ++i) g_nodeof[run + i] = bin;
        run += d;
    }
    if (tid == 255) {
        g_start2[2 * NN] = run;         // total (== 2*EE when no overflow)
        g_done = 0;                     // restore zero invariant
    }
}

// ---------------------------------------------------------------------------
// k_edge: one warp per SORTED slot (all 32768 warps busy, R4 shape). Warp w:
// widx = nodeof[w], eid = list[widx*CAP + (w - start[widx])]. Consecutive
// warps share the src row -> L1 hits. Lean body, no register src cache.
// ---------------------------------------------------------------------------
__global__ __launch_bounds__(512) void k_edge(
    const int* __restrict__ dst0, const int* __restrict__ dst1,
    const float* __restrict__ p1w1, const float* __restrict__ p1b1,
    const float* __restrict__ p1w2, const float* __restrict__ p1b2,
    const float* __restrict__ p2w1, const float* __restrict__ p2b1,
    const float* __restrict__ p2w2, const float* __restrict__ p2b2,
    float* __restrict__ out) {
    int w = (int)((blockIdx.x * blockDim.x + threadIdx.x) >> 5);
    int lane = threadIdx.x & 31;
    if (w >= __ldg(&g_start2[2 * NN])) return;  // overflow guard

    int widx = g_nodeof[w];
    int i = w - g_start2[widx];
    int eid = g_list[widx * CAP + i];
    int layer = widx >> 12;
    int node = widx & (NN - 1);
    int t = layer ? __ldg(dst1 + eid) : __ldg(dst0 + eid);

    const uint4* ps = (const uint4*)(g_Q + (size_t)node * NN) + lane;
    const uint4* pt = (const uint4*)(g_Q + (size_t)t * NN) + lane;

    int acc0 = 0, acc1 = 0, acc2 = 0, acc3 = 0;
#pragma unroll
    for (int k = 0; k < 8; k++) {
        uint4 a = ps[k * 32];
        uint4 b = pt[k * 32];
        acc0 = __dp4a((int)a.x, (int)b.x, acc0);
        acc1 = __dp4a((int)a.y, (int)b.y, acc1);
        acc2 = __dp4a((int)a.z, (int)b.z, acc2);
        acc3 = __dp4a((int)a.w, (int)b.w, acc3);
    }
    int acc = (acc0 + acc1) + (acc2 + acc3);
    acc = __reduce_add_sync(0xffffffffu, acc);

    float x = (float)acc * g_c[node] * g_c[t];

    int o = layer * PHID;
    float h0 = fmaxf(fmaf(x, p1w1[o + lane], p1b1[o + lane]), 0.f);
    float h1 = fmaxf(fmaf(x, p1w1[o + lane + 32], p1b1[o + lane + 32]), 0.f);
    float y = fmaf(h0, p1w2[o + lane], h1 * p1w2[o + lane + 32]);
#pragma unroll
    for (int off = 16; off; off >>= 1)
        y += __shfl_xor_sync(0xffffffffu, y, off);
    y += p1b2[layer];
    float x2 = 0.5f * y;  // BETA * y / LM

    float g0 = fmaxf(fmaf(x2, p2w1[o + lane], p2b1[o + lane]), 0.f);
    float g1 = fmaxf(fmaf(x2, p2w1[o + lane + 32], p2b1[o + lane + 32]), 0.f);
    float z = fmaf(g0, p2w2[o + lane], g1 * p2w2[o + lane + 32]);
#pragma unroll
    for (int off = 16; off; off >>= 1)
        z += __shfl_xor_sync(0xffffffffu, z, off);
    z += p2b2[layer];

    if (lane == 0) out[layer * EE + eid] = z;
}

extern "C" void kernel_launch(void* const* d_in, const int* in_sizes, int n_in,
                              void* d_out, int out_size) {
    const float* A    = (const float*)d_in[0];
    const int* src0   = (const int*)d_in[1];
    const int* dst0   = (const int*)d_in[2];
    const int* src1   = (const int*)d_in[3];
    const int* dst1   = (const int*)d_in[4];
    const float* f0   = (const float*)d_in[5];
    const float* f1   = (const float*)d_in[6];
    const float* p1w1 = (const float*)d_in[7];
    const float* p1b1 = (const float*)d_in[8];
    const float* p1w2 = (const float*)d_in[9];
    const float* p1b2 = (const float*)d_in[10];
    const float* p2w1 = (const float*)d_in[11];
    const float* p2b1 = (const float*)d_in[12];
    const float* p2w2 = (const float*)d_in[13];
    const float* p2b2 = (const float*)d_in[14];
    float* out = (float*)d_out;

    k_prep<<<NN / 2, 256>>>(A, f0, f1, src0, src1);
    k_edge<<<(2 * EE) / 16, 512>>>(dst0, dst1,
                                   p1w1, p1b1, p1w2, p1b2,
                                   p2w1, p2b1, p2w2, p2b2, out);
}

// round 10
// speedup vs baseline: 2.0267x; 2.0267x over previous
#include <cuda_runtime.h>
#include <cuda_bf16.h>
#include <math.h>

#define NN 4096
#define EE 16384
#define PHID 64
#define EPSF 1e-8f

// Q = round(B/scale_r) int8 (16MB, L2-resident); per-row c = scale_r/d_r.
__device__ char g_Q[(size_t)NN * NN];
__device__ float g_c[NN];

// ---------------------------------------------------------------------------
// k_prep: ONE row per CTA, 512 threads. Per-thread state: 2 float4 of A,
// 2 float4 of f_mean -> low regs, grid=4096 -> deep latency hiding.
// Computes fp32 norm + row max, quantizes row to int8 with per-row scale.
// ---------------------------------------------------------------------------
__global__ __launch_bounds__(512) void k_prep(const float* __restrict__ A,
                                              const float* __restrict__ f0,
                                              const float* __restrict__ f1) {
    __shared__ float rsum[16];
    __shared__ float rmax[16];
    __shared__ float s_cinv;
    int tid = threadIdx.x;
    int wid = tid >> 5, lane = tid & 31;
    int row = blockIdx.x;

    const float4* a4 = (const float4*)(A + (size_t)row * NN);
    float4 m[2];
    float acc = 0.f, vmax = 0.f;
#pragma unroll
    for (int it = 0; it < 2; ++it) {
        int q = tid + it * 512;
        float4 fa = ((const float4*)f0)[q];
        float4 fb = ((const float4*)f1)[q];
        float4 v = a4[q];
        m[it].x = v.x * 0.5f * (fa.x + fb.x);
        m[it].y = v.y * 0.5f * (fa.y + fb.y);
        m[it].z = v.z * 0.5f * (fa.z + fb.z);
        m[it].w = v.w * 0.5f * (fa.w + fb.w);
        float e0 = m[it].x + EPSF, e1 = m[it].y + EPSF;
        float e2 = m[it].z + EPSF, e3 = m[it].w + EPSF;
        acc += e0 * e0 + e1 * e1 + e2 * e2 + e3 * e3;
        vmax = fmaxf(vmax, fmaxf(fmaxf(fabsf(m[it].x), fabsf(m[it].y)),
                                 fmaxf(fabsf(m[it].z), fabsf(m[it].w))));
    }
#pragma unroll
    for (int off = 16; off; off >>= 1) {
        acc += __shfl_xor_sync(0xffffffffu, acc, off);
        vmax = fmaxf(vmax, __shfl_xor_sync(0xffffffffu, vmax, off));
    }
    if (lane == 0) {
        rsum[wid] = acc;
        rmax[wid] = vmax;
    }
    __syncthreads();
    if (wid == 0) {
        float t = (lane < 16) ? rsum[lane] : 0.f;
        float mx = (lane < 16) ? rmax[lane] : 0.f;
#pragma unroll
        for (int off = 8; off; off >>= 1) {
            t += __shfl_xor_sync(0xffffffffu, t, off);
            mx = fmaxf(mx, __shfl_xor_sync(0xffffffffu, mx, off));
        }
        if (lane == 0) {
            float scale = fmaxf(mx, 1e-20f) * (1.0f / 127.0f);
            g_c[row] = scale / sqrtf(t);
            s_cinv = 1.0f / scale;
        }
    }
    __syncthreads();
    float inv_scale = s_cinv;

    unsigned* qrow = (unsigned*)(g_Q + (size_t)row * NN);
#pragma unroll
    for (int it = 0; it < 2; ++it) {
        int q = tid + it * 512;
        int q0 = __float2int_rn(m[it].x * inv_scale);
        int q1 = __float2int_rn(m[it].y * inv_scale);
        int q2 = __float2int_rn(m[it].z * inv_scale);
        int q3 = __float2int_rn(m[it].w * inv_scale);
        uchar4 pk;
        pk.x = (unsigned char)(char)max(-127, min(127, q0));
        pk.y = (unsigned char)(char)max(-127, min(127, q1));
        pk.z = (unsigned char)(char)max(-127, min(127, q2));
        pk.w = (unsigned char)(char)max(-127, min(127, q3));
        qrow[q] = *(unsigned*)&pk;
    }
}

// ---------------------------------------------------------------------------
// k_edge (R4 verbatim): one warp per edge; int8 dot via dp4a (4 independent
// accumulators), REDUX.SUM, scale by c_s*c_t, two tiny 1->64->1 MLPs.
// ---------------------------------------------------------------------------
__global__ __launch_bounds__(512) void k_edge(
    const int* __restrict__ src0, const int* __restrict__ dst0,
    const int* __restrict__ src1, const int* __restrict__ dst1,
    const float* __restrict__ p1w1, const float* __restrict__ p1b1,
    const float* __restrict__ p1w2, const float* __restrict__ p1b2,
    const float* __restrict__ p2w1, const float* __restrict__ p2b1,
    const float* __restrict__ p2w2, const float* __restrict__ p2b2,
    float* __restrict__ out) {
    int gw = (int)((blockIdx.x * blockDim.x + threadIdx.x) >> 5);
    int lane = threadIdx.x & 31;
    int layer = gw >> 14;  // / EE
    int e = gw & (EE - 1);
    int s = layer ? __ldg(src1 + e) : __ldg(src0 + e);
    int t = layer ? __ldg(dst1 + e) : __ldg(dst0 + e);

    const uint4* ps = (const uint4*)(g_Q + (size_t)s * NN) + lane;
    const uint4* pt = (const uint4*)(g_Q + (size_t)t * NN) + lane;

    int acc0 = 0, acc1 = 0, acc2 = 0, acc3 = 0;
#pragma unroll
    for (int k = 0; k < 8; k++) {
        uint4 a = ps[k * 32];
        uint4 b = pt[k * 32];
        acc0 = __dp4a((int)a.x, (int)b.x, acc0);
        acc1 = __dp4a((int)a.y, (int)b.y, acc1);
        acc2 = __dp4a((int)a.z, (int)b.z, acc2);
        acc3 = __dp4a((int)a.w, (int)b.w, acc3);
    }
    int acc = (acc0 + acc1) + (acc2 + acc3);
    acc = __reduce_add_sync(0xffffffffu, acc);

    float x = (float)acc * g_c[s] * g_c[t];

    int o = layer * PHID;
    // MLP 1: 1 -> 64 -> 1 (2 hidden units per lane)
    float h0 = fmaxf(fmaf(x, p1w1[o + lane], p1b1[o + lane]), 0.f);
    float h1 = fmaxf(fmaf(x, p1w1[o + lane + 32], p1b1[o + lane + 32]), 0.f);
    float y = fmaf(h0, p1w2[o + lane], h1 * p1w2[o + lane + 32]);
#pragma unroll
    for (int off = 16; off; off >>= 1)
        y += __shfl_xor_sync(0xffffffffu, y, off);
    y += p1b2[layer];
    float x2 = 0.5f * y;  // BETA * y / LM

    // MLP 2
    float g0 = fmaxf(fmaf(x2, p2w1[o + lane], p2b1[o + lane]), 0.f);
    float g1 = fmaxf(fmaf(x2, p2w1[o + lane + 32], p2b1[o + lane + 32]), 0.f);
    float z = fmaf(g0, p2w2[o + lane], g1 * p2w2[o + lane + 32]);
#pragma unroll
    for (int off = 16; off; off >>= 1)
        z += __shfl_xor_sync(0xffffffffu, z, off);
    z += p2b2[layer];

    if (lane == 0) out[gw] = z;
}

extern "C" void kernel_launch(void* const* d_in, const int* in_sizes, int n_in,
                              void* d_out, int out_size) {
    const float* A    = (const float*)d_in[0];
    const int* src0   = (const int*)d_in[1];
    const int* dst0   = (const int*)d_in[2];
    const int* src1   = (const int*)d_in[3];
    const int* dst1   = (const int*)d_in[4];
    const float* f0   = (const float*)d_in[5];
    const float* f1   = (const float*)d_in[6];
    const float* p1w1 = (const float*)d_in[7];
    const float* p1b1 = (const float*)d_in[8];
    const float* p1w2 = (const float*)d_in[9];
    const float* p1b2 = (const float*)d_in[10];
    const float* p2w1 = (const float*)d_in[11];
    const float* p2b1 = (const float*)d_in[12];
    const float* p2w2 = (const float*)d_in[13];
    const float* p2b2 = (const float*)d_in[14];
    float* out = (float*)d_out;

    k_prep<<<NN, 512>>>(A, f0, f1);
    k_edge<<<(2 * EE) / 16, 512>>>(src0, dst0, src1, dst1,
                                   p1w1, p1b1, p1w2, p1b2,
                                   p2w1, p2b1, p2w2, p2b2, out);
}

// round 11
// speedup vs baseline: 2.3228x; 1.1461x over previous
#include <cuda_runtime.h>
#include <cuda_bf16.h>
#include <math.h>

#define NN 4096
#define EE 16384
#define PHID 64
#define EPSF 1e-8f

// Q = round(B/scale_r) int8 (16MB, L2-resident); per-row c = scale_r/d_r.
__device__ char g_Q[(size_t)NN * NN];
__device__ float g_c[NN];

// ---------------------------------------------------------------------------
// k_prep (R6 shape, measured best): 2 rows per CTA in registers; f_mean in
// registers; fused reductions; quantize to int8 with per-row scale.
// ---------------------------------------------------------------------------
__global__ __launch_bounds__(256) void k_prep(const float* __restrict__ A,
                                              const float* __restrict__ f0,
                                              const float* __restrict__ f1) {
    __shared__ float rsum[2][8];
    __shared__ float rmax[2][8];
    __shared__ float s_cinv[2];
    int tid = threadIdx.x;
    int wid = tid >> 5, lane = tid & 31;

    float4 f[4];
#pragma unroll
    for (int it = 0; it < 4; ++it) {
        int q = tid + it * 256;
        float4 a = ((const float4*)f0)[q];
        float4 b = ((const float4*)f1)[q];
        f[it].x = 0.5f * (a.x + b.x);
        f[it].y = 0.5f * (a.y + b.y);
        f[it].z = 0.5f * (a.z + b.z);
        f[it].w = 0.5f * (a.w + b.w);
    }

    float4 m[2][4];
    float acc[2], vmax[2];
#pragma unroll
    for (int r = 0; r < 2; ++r) {
        int row = blockIdx.x * 2 + r;
        const float4* a4 = (const float4*)(A + (size_t)row * NN);
        acc[r] = 0.f;
        vmax[r] = 0.f;
#pragma unroll
        for (int it = 0; it < 4; ++it) {
            float4 v = a4[tid + it * 256];
            m[r][it].x = v.x * f[it].x;
            m[r][it].y = v.y * f[it].y;
            m[r][it].z = v.z * f[it].z;
            m[r][it].w = v.w * f[it].w;
            float e0 = m[r][it].x + EPSF, e1 = m[r][it].y + EPSF;
            float e2 = m[r][it].z + EPSF, e3 = m[r][it].w + EPSF;
            acc[r] += e0 * e0 + e1 * e1 + e2 * e2 + e3 * e3;
            vmax[r] = fmaxf(vmax[r],
                            fmaxf(fmaxf(fabsf(m[r][it].x), fabsf(m[r][it].y)),
                                  fmaxf(fabsf(m[r][it].z), fabsf(m[r][it].w))));
        }
    }
#pragma unroll
    for (int off = 16; off; off >>= 1) {
#pragma unroll
        for (int r = 0; r < 2; ++r) {
            acc[r] += __shfl_xor_sync(0xffffffffu, acc[r], off);
            vmax[r] = fmaxf(vmax[r], __shfl_xor_sync(0xffffffffu, vmax[r], off));
        }
    }
    if (lane == 0) {
#pragma unroll
        for (int r = 0; r < 2; ++r) {
            rsum[r][wid] = acc[r];
            rmax[r][wid] = vmax[r];
        }
    }
    __syncthreads();
    if (tid < 2) {
        float t = 0.f, mx = 0.f;
#pragma unroll
        for (int w = 0; w < 8; w++) {
            t += rsum[tid][w];
            mx = fmaxf(mx, rmax[tid][w]);
        }
        float scale = fmaxf(mx, 1e-20f) * (1.0f / 127.0f);
        g_c[blockIdx.x * 2 + tid] = scale / sqrtf(t);
        s_cinv[tid] = 1.0f / scale;
    }
    __syncthreads();

#pragma unroll
    for (int r = 0; r < 2; ++r) {
        float inv_scale = s_cinv[r];
        uchar4 pk[4];
#pragma unroll
        for (int it = 0; it < 4; ++it) {
            int q0 = __float2int_rn(m[r][it].x * inv_scale);
            int q1 = __float2int_rn(m[r][it].y * inv_scale);
            int q2 = __float2int_rn(m[r][it].z * inv_scale);
            int q3 = __float2int_rn(m[r][it].w * inv_scale);
            pk[it].x = (unsigned char)(char)max(-127, min(127, q0));
            pk[it].y = (unsigned char)(char)max(-127, min(127, q1));
            pk[it].z = (unsigned char)(char)max(-127, min(127, q2));
            pk[it].w = (unsigned char)(char)max(-127, min(127, q3));
        }
        uint4 o;
        o.x = *(unsigned*)&pk[0];
        o.y = *(unsigned*)&pk[1];
        o.z = *(unsigned*)&pk[2];
        o.w = *(unsigned*)&pk[3];
        // fixed column permutation: dot/norm-invariant (both rows of an edge
        // share the same packing)
        ((uint4*)(g_Q + (size_t)(blockIdx.x * 2 + r) * NN))[tid] = o;
    }
}

// ---------------------------------------------------------------------------
// k_edge (R4 verbatim, measured LTS-cap floor): one warp per edge; int8 dot
// via dp4a (4 independent accumulators), REDUX.SUM, scale, two tiny MLPs.
// ---------------------------------------------------------------------------
__global__ __launch_bounds__(512) void k_edge(
    const int* __restrict__ src0, const int* __restrict__ dst0,
    const int* __restrict__ src1, const int* __restrict__ dst1,
    const float* __restrict__ p1w1, const float* __restrict__ p1b1,
    const float* __restrict__ p1w2, const float* __restrict__ p1b2,
    const float* __restrict__ p2w1, const float* __restrict__ p2b1,
    const float* __restrict__ p2w2, const float* __restrict__ p2b2,
    float* __restrict__ out) {
    int gw = (int)((blockIdx.x * blockDim.x + threadIdx.x) >> 5);
    int lane = threadIdx.x & 31;
    int layer = gw >> 14;  // / EE
    int e = gw & (EE - 1);
    int s = layer ? __ldg(src1 + e) : __ldg(src0 + e);
    int t = layer ? __ldg(dst1 + e) : __ldg(dst0 + e);

    const uint4* ps = (const uint4*)(g_Q + (size_t)s * NN) + lane;
    const uint4* pt = (const uint4*)(g_Q + (size_t)t * NN) + lane;

    int acc0 = 0, acc1 = 0, acc2 = 0, acc3 = 0;
#pragma unroll
    for (int k = 0; k < 8; k++) {
        uint4 a = ps[k * 32];
        uint4 b = pt[k * 32];
        acc0 = __dp4a((int)a.x, (int)b.x, acc0);
        acc1 = __dp4a((int)a.y, (int)b.y, acc1);
        acc2 = __dp4a((int)a.z, (int)b.z, acc2);
        acc3 = __dp4a((int)a.w, (int)b.w, acc3);
    }
    int acc = (acc0 + acc1) + (acc2 + acc3);
    acc = __reduce_add_sync(0xffffffffu, acc);

    float x = (float)acc * g_c[s] * g_c[t];

    int o = layer * PHID;
    // MLP 1: 1 -> 64 -> 1 (2 hidden units per lane)
    float h0 = fmaxf(fmaf(x, p1w1[o + lane], p1b1[o + lane]), 0.f);
    float h1 = fmaxf(fmaf(x, p1w1[o + lane + 32], p1b1[o + lane + 32]), 0.f);
    float y = fmaf(h0, p1w2[o + lane], h1 * p1w2[o + lane + 32]);
#pragma unroll
    for (int off = 16; off; off >>= 1)
        y += __shfl_xor_sync(0xffffffffu, y, off);
    y += p1b2[layer];
    float x2 = 0.5f * y;  // BETA * y / LM

    // MLP 2
    float g0 = fmaxf(fmaf(x2, p2w1[o + lane], p2b1[o + lane]), 0.f);
    float g1 = fmaxf(fmaf(x2, p2w1[o + lane + 32], p2b1[o + lane + 32]), 0.f);
    float z = fmaf(g0, p2w2[o + lane], g1 * p2w2[o + lane + 32]);
#pragma unroll
    for (int off = 16; off; off >>= 1)
        z += __shfl_xor_sync(0xffffffffu, z, off);
    z += p2b2[layer];

    if (lane == 0) out[gw] = z;
}

extern "C" void kernel_launch(void* const* d_in, const int* in_sizes, int n_in,
                              void* d_out, int out_size) {
    const float* A    = (const float*)d_in[0];
    const int* src0   = (const int*)d_in[1];
    const int* dst0   = (const int*)d_in[2];
    const int* src1   = (const int*)d_in[3];
    const int* dst1   = (const int*)d_in[4];
    const float* f0   = (const float*)d_in[5];
    const float* f1   = (const float*)d_in[6];
    const float* p1w1 = (const float*)d_in[7];
    const float* p1b1 = (const float*)d_in[8];
    const float* p1w2 = (const float*)d_in[9];
    const float* p1b2 = (const float*)d_in[10];
    const float* p2w1 = (const float*)d_in[11];
    const float* p2b1 = (const float*)d_in[12];
    const float* p2w2 = (const float*)d_in[13];
    const float* p2b2 = (const float*)d_in[14];
    float* out = (float*)d_out;

    k_prep<<<NN / 2, 256>>>(A, f0, f1);
    k_edge<<<(2 * EE) / 16, 512>>>(src0, dst0, src1, dst1,
                                   p1w1, p1b1, p1w2, p1b2,
                                   p2w1, p2b1, p2w2, p2b2, out);
}

// round 12
// speedup vs baseline: 2.3385x; 1.0067x over previous
#include <cuda_runtime.h>
#include <cuda_bf16.h>
#include <math.h>

#define NN 4096
#define EE 16384
#define PHID 64
#define EPSF 1e-8f

// Q = round(B/scale_r) int8 (16MB, L2-resident); per-row c = scale_r/d_r.
__device__ char g_Q[(size_t)NN * NN];
__device__ float g_c[NN];

// ---------------------------------------------------------------------------
// k_prep (R11, measured best): 2 rows per CTA in registers; f_mean in
// registers; fused reductions; quantize to int8 with per-row scale.
// ---------------------------------------------------------------------------
__global__ __launch_bounds__(256) void k_prep(const float* __restrict__ A,
                                              const float* __restrict__ f0,
                                              const float* __restrict__ f1) {
    __shared__ float rsum[2][8];
    __shared__ float rmax[2][8];
    __shared__ float s_cinv[2];
    int tid = threadIdx.x;
    int wid = tid >> 5, lane = tid & 31;

    float4 f[4];
#pragma unroll
    for (int it = 0; it < 4; ++it) {
        int q = tid + it * 256;
        float4 a = ((const float4*)f0)[q];
        float4 b = ((const float4*)f1)[q];
        f[it].x = 0.5f * (a.x + b.x);
        f[it].y = 0.5f * (a.y + b.y);
        f[it].z = 0.5f * (a.z + b.z);
        f[it].w = 0.5f * (a.w + b.w);
    }

    float4 m[2][4];
    float acc[2], vmax[2];
#pragma unroll
    for (int r = 0; r < 2; ++r) {
        int row = blockIdx.x * 2 + r;
        const float4* a4 = (const float4*)(A + (size_t)row * NN);
        acc[r] = 0.f;
        vmax[r] = 0.f;
#pragma unroll
        for (int it = 0; it < 4; ++it) {
            float4 v = a4[tid + it * 256];
            m[r][it].x = v.x * f[it].x;
            m[r][it].y = v.y * f[it].y;
            m[r][it].z = v.z * f[it].z;
            m[r][it].w = v.w * f[it].w;
            float e0 = m[r][it].x + EPSF, e1 = m[r][it].y + EPSF;
            float e2 = m[r][it].z + EPSF, e3 = m[r][it].w + EPSF;
            acc[r] += e0 * e0 + e1 * e1 + e2 * e2 + e3 * e3;
            vmax[r] = fmaxf(vmax[r],
                            fmaxf(fmaxf(fabsf(m[r][it].x), fabsf(m[r][it].y)),
                                  fmaxf(fabsf(m[r][it].z), fabsf(m[r][it].w))));
        }
    }
#pragma unroll
    for (int off = 16; off; off >>= 1) {
#pragma unroll
        for (int r = 0; r < 2; ++r) {
            acc[r] += __shfl_xor_sync(0xffffffffu, acc[r], off);
            vmax[r] = fmaxf(vmax[r], __shfl_xor_sync(0xffffffffu, vmax[r], off));
        }
    }
    if (lane == 0) {
#pragma unroll
        for (int r = 0; r < 2; ++r) {
            rsum[r][wid] = acc[r];
            rmax[r][wid] = vmax[r];
        }
    }
    __syncthreads();
    if (tid < 2) {
        float t = 0.f, mx = 0.f;
#pragma unroll
        for (int w = 0; w < 8; w++) {
            t += rsum[tid][w];
            mx = fmaxf(mx, rmax[tid][w]);
        }
        float scale = fmaxf(mx, 1e-20f) * (1.0f / 127.0f);
        g_c[blockIdx.x * 2 + tid] = scale / sqrtf(t);
        s_cinv[tid] = 1.0f / scale;
    }
    __syncthreads();

#pragma unroll
    for (int r = 0; r < 2; ++r) {
        float inv_scale = s_cinv[r];
        uchar4 pk[4];
#pragma unroll
        for (int it = 0; it < 4; ++it) {
            int q0 = __float2int_rn(m[r][it].x * inv_scale);
            int q1 = __float2int_rn(m[r][it].y * inv_scale);
            int q2 = __float2int_rn(m[r][it].z * inv_scale);
            int q3 = __float2int_rn(m[r][it].w * inv_scale);
            pk[it].x = (unsigned char)(char)max(-127, min(127, q0));
            pk[it].y = (unsigned char)(char)max(-127, min(127, q1));
            pk[it].z = (unsigned char)(char)max(-127, min(127, q2));
            pk[it].w = (unsigned char)(char)max(-127, min(127, q3));
        }
        uint4 o;
        o.x = *(unsigned*)&pk[0];
        o.y = *(unsigned*)&pk[1];
        o.z = *(unsigned*)&pk[2];
        o.w = *(unsigned*)&pk[3];
        // fixed column permutation: dot/norm-invariant (both rows of an edge
        // share the same packing)
        ((uint4*)(g_Q + (size_t)(blockIdx.x * 2 + r) * NN))[tid] = o;
    }
}

// ---------------------------------------------------------------------------
// k_edge: TWO edges per warp (latency-bound fix). 32 independent LDG.128,
// 8 dp4a accumulators, two REDUXes, two MLP tails with interleaved shfl
// chains. Pairs never straddle the layer boundary -> weights loaded once.
// ---------------------------------------------------------------------------
__global__ __launch_bounds__(256) void k_edge(
    const int* __restrict__ src0, const int* __restrict__ dst0,
    const int* __restrict__ src1, const int* __restrict__ dst1,
    const float* __restrict__ p1w1, const float* __restrict__ p1b1,
    const float* __restrict__ p1w2, const float* __restrict__ p1b2,
    const float* __restrict__ p2w1, const float* __restrict__ p2b1,
    const float* __restrict__ p2w2, const float* __restrict__ p2b2,
    float* __restrict__ out) {
    int w = (int)((blockIdx.x * blockDim.x + threadIdx.x) >> 5);  // 0..16383
    int lane = threadIdx.x & 31;
    int layer = w >> 13;            // (2w)>>14
    int e0 = (2 * w) & (EE - 1);
    int e1 = e0 + 1;

    const int* src = layer ? src1 : src0;
    const int* dst = layer ? dst1 : dst0;
    int s0 = __ldg(src + e0), t0 = __ldg(dst + e0);
    int s1 = __ldg(src + e1), t1 = __ldg(dst + e1);

    const uint4* ps0 = (const uint4*)(g_Q + (size_t)s0 * NN) + lane;
    const uint4* pt0 = (const uint4*)(g_Q + (size_t)t0 * NN) + lane;
    const uint4* ps1 = (const uint4*)(g_Q + (size_t)s1 * NN) + lane;
    const uint4* pt1 = (const uint4*)(g_Q + (size_t)t1 * NN) + lane;

    int a0 = 0, a1 = 0, a2 = 0, a3 = 0;
    int b0 = 0, b1 = 0, b2 = 0, b3 = 0;
#pragma unroll
    for (int k = 0; k < 8; k++) {
        uint4 xa = ps0[k * 32];
        uint4 xb = pt0[k * 32];
        uint4 ya = ps1[k * 32];
        uint4 yb = pt1[k * 32];
        a0 = __dp4a((int)xa.x, (int)xb.x, a0);
        b0 = __dp4a((int)ya.x, (int)yb.x, b0);
        a1 = __dp4a((int)xa.y, (int)xb.y, a1);
        b1 = __dp4a((int)ya.y, (int)yb.y, b1);
        a2 = __dp4a((int)xa.z, (int)xb.z, a2);
        b2 = __dp4a((int)ya.z, (int)yb.z, b2);
        a3 = __dp4a((int)xa.w, (int)xb.w, a3);
        b3 = __dp4a((int)ya.w, (int)yb.w, b3);
    }
    int accA = (a0 + a1) + (a2 + a3);
    int accB = (b0 + b1) + (b2 + b3);
    accA = __reduce_add_sync(0xffffffffu, accA);
    accB = __reduce_add_sync(0xffffffffu, accB);

    float x0 = (float)accA * g_c[s0] * g_c[t0];
    float x1 = (float)accB * g_c[s1] * g_c[t1];

    int o = layer * PHID;
    float w1a = p1w1[o + lane], w1b = p1w1[o + lane + 32];
    float c1a = p1b1[o + lane], c1b = p1b1[o + lane + 32];
    float v1a = p1w2[o + lane], v1b = p1w2[o + lane + 32];
    float bias1 = p1b2[layer], bias2 = p2b2[layer];

    // MLP 1 for both edges, interleaved
    float h0A = fmaxf(fmaf(x0, w1a, c1a), 0.f);
    float h0B = fmaxf(fmaf(x1, w1a, c1a), 0.f);
    float h1A = fmaxf(fmaf(x0, w1b, c1b), 0.f);
    float h1B = fmaxf(fmaf(x1, w1b, c1b), 0.f);
    float yA = fmaf(h0A, v1a, h1A * v1b);
    float yB = fmaf(h0B, v1a, h1B * v1b);
#pragma unroll
    for (int off = 16; off; off >>= 1) {
        yA += __shfl_xor_sync(0xffffffffu, yA, off);
        yB += __shfl_xor_sync(0xffffffffu, yB, off);
    }
    float x2A = 0.5f * (yA + bias1);
    float x2B = 0.5f * (yB + bias1);

    float w2a = p2w1[o + lane], w2b = p2w1[o + lane + 32];
    float c2a = p2b1[o + lane], c2b = p2b1[o + lane + 32];
    float v2a = p2w2[o + lane], v2b = p2w2[o + lane + 32];

    // MLP 2 for both edges, interleaved
    float g0A = fmaxf(fmaf(x2A, w2a, c2a), 0.f);
    float g0B = fmaxf(fmaf(x2B, w2a, c2a), 0.f);
    float g1A = fmaxf(fmaf(x2A, w2b, c2b), 0.f);
    float g1B = fmaxf(fmaf(x2B, w2b, c2b), 0.f);
    float zA = fmaf(g0A, v2a, g1A * v2b);
    float zB = fmaf(g0B, v2a, g1B * v2b);
#pragma unroll
    for (int off = 16; off; off >>= 1) {
        zA += __shfl_xor_sync(0xffffffffu, zA, off);
        zB += __shfl_xor_sync(0xffffffffu, zB, off);
    }
    zA += bias2;
    zB += bias2;

    if (lane == 0) {
        float2 zz = make_float2(zA, zB);
        *(float2*)(out + 2 * w) = zz;   // 2w even -> 8B aligned
    }
}

extern "C" void kernel_launch(void* const* d_in, const int* in_sizes, int n_in,
                              void* d_out, int out_size) {
    const float* A    = (const float*)d_in[0];
    const int* src0   = (const int*)d_in[1];
    const int* dst0   = (const int*)d_in[2];
    const int* src1   = (const int*)d_in[3];
    const int* dst1   = (const int*)d_in[4];
    const float* f0   = (const float*)d_in[5];
    const float* f1   = (const float*)d_in[6];
    const float* p1w1 = (const float*)d_in[7];
    const float* p1b1 = (const float*)d_in[8];
    const float* p1w2 = (const float*)d_in[9];
    const float* p1b2 = (const float*)d_in[10];
    const float* p2w1 = (const float*)d_in[11];
    const float* p2b1 = (const float*)d_in[12];
    const float* p2w2 = (const float*)d_in[13];
    const float* p2b2 = (const float*)d_in[14];
    float* out = (float*)d_out;

    k_prep<<<NN / 2, 256>>>(A, f0, f1);
    // 16384 warps, 8 warps per 256-thread CTA -> 2048 CTAs
    k_edge<<<2048, 256>>>(src0, dst0, src1, dst1,
                          p1w1, p1b1, p1w2, p1b2,
                          p2w1, p2b1, p2w2, p2b2, out);
}